// round 12
// baseline (speedup 1.0000x reference)
#include <cuda_runtime.h>
#include <cuda_bf16.h>
#include <cstdint>

#define N_NODES 50000
#define EMAX    1000000
#define CH      128

// ---------------------------------------------------------------------------
// Scratch (device globals -- no allocation allowed)
// ---------------------------------------------------------------------------
__device__ __align__(16) float g_h1[(size_t)N_NODES * CH];
__device__ __align__(16) __nv_bfloat16 g_Xhi[(size_t)N_NODES * CH]; // h2 hi
__device__ __align__(16) __nv_bfloat16 g_Xlo[(size_t)N_NODES * CH]; // h2 lo
__device__ int g_cnt[N_NODES];
__device__ int g_row[N_NODES + 1];
__device__ int g_cursor[N_NODES];
__device__ int g_bsum[64];
__device__ int g_boff[64];
__device__ int g_col[EMAX];
__device__ int g_is64;

// transposed weights Bt[n][k] (k contiguous), bf16 hi/lo
__device__ __align__(16) __nv_bfloat16 g_W1t_hi[128 * 256];
__device__ __align__(16) __nv_bfloat16 g_W1t_lo[128 * 256];
__device__ __align__(16) __nv_bfloat16 g_W2t_hi[128 * 256];
__device__ __align__(16) __nv_bfloat16 g_W2t_lo[128 * 256];
__device__ __align__(16) __nv_bfloat16 g_Wdt_hi[128 * 128];
__device__ __align__(16) __nv_bfloat16 g_Wdt_lo[128 * 128];

__device__ __forceinline__ void bfsplit(float v, __nv_bfloat16& h, __nv_bfloat16& l) {
    h = __float2bfloat16(v);
    l = __float2bfloat16(v - __bfloat162float(h));
}
__device__ __forceinline__ uint32_t bf2_hi(float x, float y) {
    __nv_bfloat162 h = __floats2bfloat162_rn(x, y);
    return *(uint32_t*)&h;
}

// ---------------------------------------------------------------------------
// edge index read (int32 vs int64 runtime-detected)
// ---------------------------------------------------------------------------
__device__ __forceinline__ int edge_at(const void* e, int i) {
    return g_is64 ? (int)((const long long*)e)[i] : ((const int*)e)[i];
}

__global__ void detect_kernel(const unsigned* __restrict__ e) {
    __shared__ unsigned red[256];
    unsigned acc = 0;
    int t = threadIdx.x;
    #pragma unroll
    for (int j = 0; j < 8; j++) acc |= e[(t * 8 + j) * 2 + 1];
    red[t] = acc;
    __syncthreads();
    for (int s = 128; s > 0; s >>= 1) {
        if (t < s) red[t] |= red[t + s];
        __syncthreads();
    }
    if (t == 0) g_is64 = (red[0] == 0) ? 1 : 0;
}

// ---------------------------------------------------------------------------
// prep_w: transpose + bf16-split all weights once (81920 elements)
// ---------------------------------------------------------------------------
__global__ void prep_w_kernel(const float* __restrict__ W1l,
                              const float* __restrict__ W1r,
                              const float* __restrict__ W2l,
                              const float* __restrict__ W2r,
                              const float* __restrict__ Wd) {
    int idx = blockIdx.x * blockDim.x + threadIdx.x;
    if (idx < 32768) {
        int nn = idx >> 8, k = idx & 255;
        float v = (k < 128) ? W1l[(size_t)k * CH + nn]
                            : W1r[(size_t)(k - 128) * CH + nn];
        bfsplit(v, g_W1t_hi[nn * 256 + k], g_W1t_lo[nn * 256 + k]);
    } else if (idx < 65536) {
        int r = idx - 32768;
        int nn = r >> 8, k = r & 255;
        float v = (k < 128) ? W2l[(size_t)k * CH + nn]
                            : W2r[(size_t)(k - 128) * CH + nn];
        bfsplit(v, g_W2t_hi[nn * 256 + k], g_W2t_lo[nn * 256 + k]);
    } else if (idx < 81920) {
        int r = idx - 65536;
        int nn = r >> 7, k = r & 127;
        float v = Wd[(size_t)k * CH + nn];
        bfsplit(v, g_Wdt_hi[nn * 128 + k], g_Wdt_lo[nn * 128 + k]);
    }
}

// ---------------------------------------------------------------------------
// CSR build: histogram -> scan -> fill (proven R11)
// ---------------------------------------------------------------------------
__global__ void clear_cnt_kernel(int n) {
    int i = blockIdx.x * blockDim.x + threadIdx.x;
    if (i < n) g_cnt[i] = 0;
}

__global__ void hist_kernel(const void* __restrict__ edge, int E, int n) {
    int i = blockIdx.x * blockDim.x + threadIdx.x;
    if (i >= E) return;
    int d = edge_at(edge, E + i);
    if ((unsigned)d < (unsigned)n) atomicAdd(&g_cnt[d], 1);
}

__global__ void scan1_kernel(int n) {
    __shared__ int sh[1024];
    int t = threadIdx.x;
    int idx = blockIdx.x * 1024 + t;
    int v = (idx < n) ? g_cnt[idx] : 0;
    sh[t] = v;
    __syncthreads();
    #pragma unroll
    for (int off = 1; off < 1024; off <<= 1) {
        int add = (t >= off) ? sh[t - off] : 0;
        __syncthreads();
        sh[t] += add;
        __syncthreads();
    }
    if (idx < n) g_row[idx] = sh[t] - v;
    if (t == 1023) g_bsum[blockIdx.x] = sh[1023];
}

__global__ void scan2_kernel(int nb) {
    __shared__ int sh[64];
    int t = threadIdx.x;
    sh[t] = (t < nb) ? g_bsum[t] : 0;
    __syncthreads();
    if (t == 0) {
        int run = 0;
        for (int i = 0; i < nb; i++) {
            g_boff[i] = run;
            run += sh[i];
        }
    }
}

__global__ void scan3_kernel(int n, int E) {
    int idx = blockIdx.x * 1024 + threadIdx.x;
    if (idx < n) {
        g_row[idx] += g_boff[blockIdx.x];
        g_cursor[idx] = 0;
    }
    if (idx == 0) g_row[n] = E;
}

__global__ void fill_kernel(const void* __restrict__ edge, int E, int n) {
    int i = blockIdx.x * blockDim.x + threadIdx.x;
    if (i >= E) return;
    int s = edge_at(edge, i);
    int d = edge_at(edge, E + i);
    if ((unsigned)d >= (unsigned)n) return;
    if ((unsigned)s >= (unsigned)n) s = 0;
    int pos = g_row[d] + atomicAdd(&g_cursor[d], 1);
    g_col[pos] = s;
}

// ---------------------------------------------------------------------------
// Fused GEMM: gather-mean (CSR) -> smem bf16 hi/lo -> mma.sync bf16x3.
// BM=64, BN=128, KC=32. 8 warps in 2(M) x 4(N); warp tile 32x32.
// Dynamic smem: AggHi/AggLo [64][136] + B double-buffer [2][128][40] + bias.
// MODE 1: relu( [mean(x_nbr) | x ] @ [W1_l;W1_r] + b1 ) -> g_h1
// MODE 2: relu( [mean(h1_nbr)| h1] @ [W2_l;W2_r] + b2 ) -> g_Xhi/lo (h2 bf16)
// MODE 3: alpha*(h2 @ Wd + bd) + (1-alpha)*xres        -> out_ext
// ---------------------------------------------------------------------------
#define BM 64
#define KC 32
#define AGG_STR 136   // 68 words == 4 mod 32 -> conflict-free fragments
#define BSTR 40       // 20 words == 20 mod 32 -> conflict-free (proven)

#define OFF_AGGHI 0
#define OFF_AGGLO 17408
#define OFF_BH    34816
#define OFF_BL    55296
#define OFF_BIAS  75776
#define SMEM_SZ   76288

__device__ __forceinline__ void mma_bf16(float* d, const uint32_t* a,
                                         const uint32_t* b) {
    asm volatile(
        "mma.sync.aligned.m16n8k16.row.col.f32.bf16.bf16.f32 "
        "{%0,%1,%2,%3}, {%4,%5,%6,%7}, {%8,%9}, {%0,%1,%2,%3};"
        : "+f"(d[0]), "+f"(d[1]), "+f"(d[2]), "+f"(d[3])
        : "r"(a[0]), "r"(a[1]), "r"(a[2]), "r"(a[3]), "r"(b[0]), "r"(b[1]));
}

template <int MODE>
__global__ __launch_bounds__(256) void gemm_kernel(
    const float* __restrict__ feat,    // MODE 1: x, MODE 2: g_h1 (via null)
    const float* __restrict__ bias,
    const float* __restrict__ xres,    // MODE 3
    const float* __restrict__ alpha_p, // MODE 3
    float* __restrict__ out_ext,       // MODE 3
    int n)
{
    extern __shared__ __align__(16) char dsm[];
    __nv_bfloat16 (*AggHi)[AGG_STR] =
        reinterpret_cast<__nv_bfloat16(*)[AGG_STR]>(dsm + OFF_AGGHI);
    __nv_bfloat16 (*AggLo)[AGG_STR] =
        reinterpret_cast<__nv_bfloat16(*)[AGG_STR]>(dsm + OFF_AGGLO);
    __nv_bfloat16 (*BH)[128][BSTR] =
        reinterpret_cast<__nv_bfloat16(*)[128][BSTR]>(dsm + OFF_BH);
    __nv_bfloat16 (*BL)[128][BSTR] =
        reinterpret_cast<__nv_bfloat16(*)[128][BSTR]>(dsm + OFF_BL);
    float* s_bias = (float*)(dsm + OFF_BIAS);

    int t = threadIdx.x;
    int lane = t & 31;
    int w = t >> 5;
    int wm = w >> 2;
    int wn = w & 3;
    int block_row = blockIdx.x * BM;

    const float* featp = (MODE == 2) ? g_h1 : feat;

    if (t < 128) s_bias[t] = bias[t];

    // ---- phase 0: fill Agg buffers ----
    if (MODE != 3) {
        // gather-mean: warp w handles rows w*8 .. w*8+7
        #pragma unroll 1
        for (int rr = 0; rr < 8; rr++) {
            int r = w * 8 + rr;
            int gr = block_row + r;
            float a0 = 0.f, a1 = 0.f, a2 = 0.f, a3 = 0.f;
            float sc = 0.f;
            if (gr < n) {
                int base = g_row[gr];
                int end  = g_row[gr + 1];
                sc = 1.0f / fmaxf((float)(end - base), 1.0f);
                int j = base;
                for (; j + 3 < end; j += 4) {
                    int s0 = g_col[j],     s1 = g_col[j + 1];
                    int s2 = g_col[j + 2], s3 = g_col[j + 3];
                    float4 v0 = *(const float4*)(featp + (size_t)s0 * CH + lane * 4);
                    float4 v1 = *(const float4*)(featp + (size_t)s1 * CH + lane * 4);
                    float4 v2 = *(const float4*)(featp + (size_t)s2 * CH + lane * 4);
                    float4 v3 = *(const float4*)(featp + (size_t)s3 * CH + lane * 4);
                    a0 += (v0.x + v1.x) + (v2.x + v3.x);
                    a1 += (v0.y + v1.y) + (v2.y + v3.y);
                    a2 += (v0.z + v1.z) + (v2.z + v3.z);
                    a3 += (v0.w + v1.w) + (v2.w + v3.w);
                }
                for (; j < end; j++) {
                    int s0 = g_col[j];
                    float4 v0 = *(const float4*)(featp + (size_t)s0 * CH + lane * 4);
                    a0 += v0.x; a1 += v0.y; a2 += v0.z; a3 += v0.w;
                }
            }
            a0 *= sc; a1 *= sc; a2 *= sc; a3 *= sc;
            __nv_bfloat162 h01, h23, l01, l23;
            bfsplit(a0, h01.x, l01.x);  bfsplit(a1, h01.y, l01.y);
            bfsplit(a2, h23.x, l23.x);  bfsplit(a3, h23.y, l23.y);
            *(uint2*)&AggHi[r][lane * 4] =
                make_uint2(*(uint32_t*)&h01, *(uint32_t*)&h23);
            *(uint2*)&AggLo[r][lane * 4] =
                make_uint2(*(uint32_t*)&l01, *(uint32_t*)&l23);
        }
    } else {
        // copy preconverted h2 (bf16 hi/lo) full-width
        int row = t >> 2;
        int cs = (t & 3) * 32;
        int gr = block_row + row;
        uint4 z = make_uint4(0, 0, 0, 0);
        #pragma unroll
        for (int i = 0; i < 4; i++) {
            uint4 vh = z, vl = z;
            if (gr < n) {
                size_t go = (size_t)gr * CH + cs + i * 8;
                vh = *(const uint4*)(g_Xhi + go);
                vl = *(const uint4*)(g_Xlo + go);
            }
            *(uint4*)&AggHi[row][cs + i * 8] = vh;
            *(uint4*)&AggLo[row][cs + i * 8] = vl;
        }
    }

    const int NCH = (MODE == 3) ? 4 : 8;
    const int KB  = (MODE == 3) ? 128 : 256;
    const __nv_bfloat16* wh = (MODE == 1) ? g_W1t_hi
                            : (MODE == 2) ? g_W2t_hi : g_Wdt_hi;
    const __nv_bfloat16* wl = (MODE == 1) ? g_W1t_lo
                            : (MODE == 2) ? g_W2t_lo : g_Wdt_lo;

    int bnn = t >> 1;            // 0..127
    int bks = (t & 1) * 16;      // 0,16

    // stage B chunk 0 into buffer 0
    {
        size_t go = (size_t)bnn * KB + bks;
        *(uint4*)&BH[0][bnn][bks]     = *(const uint4*)(wh + go);
        *(uint4*)&BH[0][bnn][bks + 8] = *(const uint4*)(wh + go + 8);
        *(uint4*)&BL[0][bnn][bks]     = *(const uint4*)(wl + go);
        *(uint4*)&BL[0][bnn][bks + 8] = *(const uint4*)(wl + go + 8);
    }
    __syncthreads();

    float acc[2][4][4];
    #pragma unroll
    for (int mi = 0; mi < 2; mi++)
        #pragma unroll
        for (int nj = 0; nj < 4; nj++)
            #pragma unroll
            for (int q = 0; q < 4; q++) acc[mi][nj][q] = 0.f;

    #pragma unroll 1
    for (int c = 0; c < NCH; c++) {
        int buf = c & 1;

        // prefetch next B chunk into regs (overlaps mma)
        uint4 nb0, nb1, nb2, nb3;
        if (c + 1 < NCH) {
            size_t go = (size_t)bnn * KB + (c + 1) * KC + bks;
            nb0 = *(const uint4*)(wh + go);
            nb1 = *(const uint4*)(wh + go + 8);
            nb2 = *(const uint4*)(wl + go);
            nb3 = *(const uint4*)(wl + go + 8);
        }

        // ---- mma: 2 k16-steps, 3 passes (R11-proven fragment layout) ----
        int kofsA = (c & 3) * KC;
        #pragma unroll
        for (int kk = 0; kk < KC; kk += 16) {
            int kw = kk + (lane & 3) * 2;
            int rr = wm * 32 + (lane >> 2);
            uint32_t a_hi[2][4], a_lo[2][4], b_hi[4][2], b_lo[4][2];
            #pragma unroll
            for (int mi = 0; mi < 2; mi++) {
                int r = rr + mi * 16;
                a_hi[mi][0] = *(uint32_t*)&AggHi[r][kofsA + kw];
                a_hi[mi][1] = *(uint32_t*)&AggHi[r + 8][kofsA + kw];
                a_hi[mi][2] = *(uint32_t*)&AggHi[r][kofsA + kw + 8];
                a_hi[mi][3] = *(uint32_t*)&AggHi[r + 8][kofsA + kw + 8];
                a_lo[mi][0] = *(uint32_t*)&AggLo[r][kofsA + kw];
                a_lo[mi][1] = *(uint32_t*)&AggLo[r + 8][kofsA + kw];
                a_lo[mi][2] = *(uint32_t*)&AggLo[r][kofsA + kw + 8];
                a_lo[mi][3] = *(uint32_t*)&AggLo[r + 8][kofsA + kw + 8];
            }
            #pragma unroll
            for (int nj = 0; nj < 4; nj++) {
                int cn = wn * 32 + nj * 8 + (lane >> 2);
                b_hi[nj][0] = *(uint32_t*)&BH[buf][cn][kw];
                b_hi[nj][1] = *(uint32_t*)&BH[buf][cn][kw + 8];
                b_lo[nj][0] = *(uint32_t*)&BL[buf][cn][kw];
                b_lo[nj][1] = *(uint32_t*)&BL[buf][cn][kw + 8];
            }
            #pragma unroll
            for (int mi = 0; mi < 2; mi++)
                #pragma unroll
                for (int nj = 0; nj < 4; nj++) {
                    mma_bf16(acc[mi][nj], a_hi[mi], b_hi[nj]);
                    mma_bf16(acc[mi][nj], a_hi[mi], b_lo[nj]);
                    mma_bf16(acc[mi][nj], a_lo[mi], b_hi[nj]);
                }
        }

        if (c + 1 < NCH) {
            if (MODE != 3 && c == 3) {
                // switch Agg buffers from aggregated to self features
                __syncthreads();     // all warps done with agg chunks
                int row = t >> 2;
                int cs = (t & 3) * 32;
                int gr = block_row + row;
                #pragma unroll
                for (int i = 0; i < 8; i++) {
                    float4 v = make_float4(0.f, 0.f, 0.f, 0.f);
                    if (gr < n)
                        v = *(const float4*)(featp + (size_t)gr * CH + cs + i * 4);
                    uint32_t h0 = bf2_hi(v.x, v.y);
                    uint32_t h1 = bf2_hi(v.z, v.w);
                    float2 f0 = __bfloat1622float2(*(__nv_bfloat162*)&h0);
                    float2 f1 = __bfloat1622float2(*(__nv_bfloat162*)&h1);
                    uint32_t l0 = bf2_hi(v.x - f0.x, v.y - f0.y);
                    uint32_t l1 = bf2_hi(v.z - f1.x, v.w - f1.y);
                    *(uint2*)&AggHi[row][cs + i * 4] = make_uint2(h0, h1);
                    *(uint2*)&AggLo[row][cs + i * 4] = make_uint2(l0, l1);
                }
            }
            // store prefetched B into the other buffer
            *(uint4*)&BH[buf ^ 1][bnn][bks]     = nb0;
            *(uint4*)&BH[buf ^ 1][bnn][bks + 8] = nb1;
            *(uint4*)&BL[buf ^ 1][bnn][bks]     = nb2;
            *(uint4*)&BL[buf ^ 1][bnn][bks + 8] = nb3;
            __syncthreads();
        }
    }

    // ---- epilogue ----
    float alpha = 0.f, one_m = 0.f;
    if (MODE == 3) { alpha = *alpha_p; one_m = 1.0f - alpha; }

    #pragma unroll
    for (int mi = 0; mi < 2; mi++) {
        #pragma unroll
        for (int part = 0; part < 2; part++) {
            int grow = block_row + wm * 32 + mi * 16 + part * 8 + (lane >> 2);
            if (grow < n) {
                #pragma unroll
                for (int nj = 0; nj < 4; nj++) {
                    int gcol = wn * 32 + nj * 8 + (lane & 3) * 2;
                    float v0 = acc[mi][nj][part * 2 + 0] + s_bias[gcol];
                    float v1 = acc[mi][nj][part * 2 + 1] + s_bias[gcol + 1];
                    size_t o = (size_t)grow * CH + gcol;
                    if (MODE == 3) {
                        float2 xv = *(const float2*)(xres + o);
                        float2 ov;
                        ov.x = alpha * v0 + one_m * xv.x;
                        ov.y = alpha * v1 + one_m * xv.y;
                        *(float2*)(out_ext + o) = ov;
                    } else if (MODE == 1) {
                        float2 ov;
                        ov.x = fmaxf(v0, 0.f);
                        ov.y = fmaxf(v1, 0.f);
                        *(float2*)(g_h1 + o) = ov;
                    } else {  // MODE 2: h2 as bf16 hi/lo only
                        v0 = fmaxf(v0, 0.f);
                        v1 = fmaxf(v1, 0.f);
                        __nv_bfloat162 h, l;
                        bfsplit(v0, h.x, l.x);
                        bfsplit(v1, h.y, l.y);
                        *(uint32_t*)(g_Xhi + o) = *(uint32_t*)&h;
                        *(uint32_t*)(g_Xlo + o) = *(uint32_t*)&l;
                    }
                }
            }
        }
    }
}

// ---------------------------------------------------------------------------
extern "C" void kernel_launch(void* const* d_in, const int* in_sizes, int n_in,
                              void* d_out, int out_size) {
    const float* x     = (const float*)d_in[0];
    const void*  edge  = d_in[1];
    const float* W1_l  = (const float*)d_in[2];
    const float* b1    = (const float*)d_in[3];
    const float* W1_r  = (const float*)d_in[4];
    const float* W2_l  = (const float*)d_in[5];
    const float* b2    = (const float*)d_in[6];
    const float* W2_r  = (const float*)d_in[7];
    const float* Wd    = (const float*)d_in[8];
    const float* bd    = (const float*)d_in[9];
    const float* alpha = (const float*)d_in[10];
    float* out = (float*)d_out;

    int n = in_sizes[0] / CH;            // 50000
    int E = in_sizes[1] / 2;             // 640000
    if (E > EMAX) E = EMAX;

    int eb = (E + 255) / 256;
    int nb = (n + 255) / 256;
    int sb = (n + 1023) / 1024;
    int gb = (n + BM - 1) / BM;          // 782

    cudaFuncSetAttribute(gemm_kernel<1>,
        cudaFuncAttributeMaxDynamicSharedMemorySize, SMEM_SZ);
    cudaFuncSetAttribute(gemm_kernel<2>,
        cudaFuncAttributeMaxDynamicSharedMemorySize, SMEM_SZ);
    cudaFuncSetAttribute(gemm_kernel<3>,
        cudaFuncAttributeMaxDynamicSharedMemorySize, SMEM_SZ);

    // CSR build + weight prep (once)
    detect_kernel<<<1, 256>>>((const unsigned*)edge);
    prep_w_kernel<<<320, 256>>>(W1_l, W1_r, W2_l, W2_r, Wd);
    clear_cnt_kernel<<<nb, 256>>>(n);
    hist_kernel<<<eb, 256>>>(edge, E, n);
    scan1_kernel<<<sb, 1024>>>(n);
    scan2_kernel<<<1, 64>>>(sb);
    scan3_kernel<<<sb, 1024>>>(n, E);
    fill_kernel<<<eb, 256>>>(edge, E, n);

    // Layer 1 (fused gather + GEMM)
    gemm_kernel<1><<<gb, 256, SMEM_SZ>>>(x, b1, nullptr, nullptr, nullptr, n);
    // Layer 2
    gemm_kernel<2><<<gb, 256, SMEM_SZ>>>(nullptr, b2, nullptr, nullptr, nullptr, n);
    // Decoder + residual
    gemm_kernel<3><<<gb, 256, SMEM_SZ>>>(nullptr, bd, x, alpha, out, n);
}

// round 13
// speedup vs baseline: 1.1833x; 1.1833x over previous
#include <cuda_runtime.h>
#include <cuda_bf16.h>
#include <cstdint>

#define N_NODES 50000
#define EMAX    1000000
#define CH      128

// Scratch (device globals -- no allocation allowed)
__device__ __align__(16) float g_agg[(size_t)N_NODES * CH];
__device__ __align__(16) float g_h1[(size_t)N_NODES * CH];
__device__ int g_cnt[N_NODES];
__device__ int g_row[N_NODES + 1];
__device__ int g_cursor[N_NODES];
__device__ int g_bsum[64];
__device__ int g_boff[64];
__device__ int g_col[EMAX];
__device__ int g_is64;

// ---------------------------------------------------------------------------
// edge index read (int32 vs int64 runtime-detected)
// ---------------------------------------------------------------------------
__device__ __forceinline__ int edge_at(const void* e, int i) {
    return g_is64 ? (int)((const long long*)e)[i] : ((const int*)e)[i];
}

__global__ void detect_kernel(const unsigned* __restrict__ e) {
    __shared__ unsigned red[256];
    unsigned acc = 0;
    int t = threadIdx.x;
    #pragma unroll
    for (int j = 0; j < 8; j++) acc |= e[(t * 8 + j) * 2 + 1];
    red[t] = acc;
    __syncthreads();
    for (int s = 128; s > 0; s >>= 1) {
        if (t < s) red[t] |= red[t + s];
        __syncthreads();
    }
    if (t == 0) g_is64 = (red[0] == 0) ? 1 : 0;
}

// ---------------------------------------------------------------------------
// CSR build: histogram -> scan -> fill (proven R11)
// ---------------------------------------------------------------------------
__global__ void clear_cnt_kernel(int n) {
    int i = blockIdx.x * blockDim.x + threadIdx.x;
    if (i < n) g_cnt[i] = 0;
}

__global__ void hist_kernel(const void* __restrict__ edge, int E, int n) {
    int i = blockIdx.x * blockDim.x + threadIdx.x;
    if (i >= E) return;
    int d = edge_at(edge, E + i);
    if ((unsigned)d < (unsigned)n) atomicAdd(&g_cnt[d], 1);
}

__global__ void scan1_kernel(int n) {
    __shared__ int sh[1024];
    int t = threadIdx.x;
    int idx = blockIdx.x * 1024 + t;
    int v = (idx < n) ? g_cnt[idx] : 0;
    sh[t] = v;
    __syncthreads();
    #pragma unroll
    for (int off = 1; off < 1024; off <<= 1) {
        int add = (t >= off) ? sh[t - off] : 0;
        __syncthreads();
        sh[t] += add;
        __syncthreads();
    }
    if (idx < n) g_row[idx] = sh[t] - v;
    if (t == 1023) g_bsum[blockIdx.x] = sh[1023];
}

__global__ void scan2_kernel(int nb) {
    __shared__ int sh[64];
    int t = threadIdx.x;
    sh[t] = (t < nb) ? g_bsum[t] : 0;
    __syncthreads();
    if (t == 0) {
        int run = 0;
        for (int i = 0; i < nb; i++) {
            g_boff[i] = run;
            run += sh[i];
        }
    }
}

__global__ void scan3_kernel(int n, int E) {
    int idx = blockIdx.x * 1024 + threadIdx.x;
    if (idx < n) {
        g_row[idx] += g_boff[blockIdx.x];
        g_cursor[idx] = 0;
    }
    if (idx == 0) g_row[n] = E;
}

__global__ void fill_kernel(const void* __restrict__ edge, int E, int n) {
    int i = blockIdx.x * blockDim.x + threadIdx.x;
    if (i >= E) return;
    int s = edge_at(edge, i);
    int d = edge_at(edge, E + i);
    if ((unsigned)d >= (unsigned)n) return;
    if ((unsigned)s >= (unsigned)n) s = 0;
    int pos = g_row[d] + atomicAdd(&g_cursor[d], 1);
    g_col[pos] = s;
}

// ---------------------------------------------------------------------------
// aggregate: one warp per destination row, pure gather, mean folded in.
// SRC 0: feat = x (param). SRC 1: feat = g_h1. Output: g_agg (pre-scaled).
// ---------------------------------------------------------------------------
template <int SRC>
__global__ void aggregate_kernel(const float* __restrict__ feat_ext, int n) {
    int row = (blockIdx.x * blockDim.x + threadIdx.x) >> 5;
    int lane = threadIdx.x & 31;
    if (row >= n) return;

    const float* __restrict__ feat = (SRC == 0) ? feat_ext : g_h1;

    int base = g_row[row];
    int end  = g_row[row + 1];
    int deg  = end - base;

    float a0 = 0.f, a1 = 0.f, a2 = 0.f, a3 = 0.f;
    int j = base;
    for (; j + 3 < end; j += 4) {
        int s0 = g_col[j],     s1 = g_col[j + 1];
        int s2 = g_col[j + 2], s3 = g_col[j + 3];
        float4 v0 = *(const float4*)(feat + (size_t)s0 * CH + lane * 4);
        float4 v1 = *(const float4*)(feat + (size_t)s1 * CH + lane * 4);
        float4 v2 = *(const float4*)(feat + (size_t)s2 * CH + lane * 4);
        float4 v3 = *(const float4*)(feat + (size_t)s3 * CH + lane * 4);
        a0 += (v0.x + v1.x) + (v2.x + v3.x);
        a1 += (v0.y + v1.y) + (v2.y + v3.y);
        a2 += (v0.z + v1.z) + (v2.z + v3.z);
        a3 += (v0.w + v1.w) + (v2.w + v3.w);
    }
    for (; j < end; j++) {
        int s0 = g_col[j];
        float4 v0 = *(const float4*)(feat + (size_t)s0 * CH + lane * 4);
        a0 += v0.x; a1 += v0.y; a2 += v0.z; a3 += v0.w;
    }

    float sc = 1.0f / fmaxf((float)deg, 1.0f);
    float4 o = make_float4(a0 * sc, a1 * sc, a2 * sc, a3 * sc);
    *(float4*)(g_agg + (size_t)row * CH + lane * 4) = o;
}

// ---------------------------------------------------------------------------
// GEMM via mma.sync m16n8k16 bf16 (HMMA), bf16x3 split (proven R8/R11 math).
// BM=128, BN=128, KC=32. 8 warps in 2(M) x 4(N); warp tile 64x32 (4 M-frags).
// g_agg is pre-scaled by 1/deg (mean folded into aggregate).
// MODE 1: relu( [agg | x ] @ [W1_l;W1_r] + b1 ) -> g_h1     (K=256)
// MODE 2: relu( [agg | h1] @ [W2_l;W2_r] + b2 ) -> g_agg (h2)
// MODE 3: alpha*(g_agg @ Wd + bd) + (1-alpha)*xres -> out_ext (K=128)
// ---------------------------------------------------------------------------
#define BM 128
#define KC 32
#define ASTR 40

__device__ __forceinline__ void mma_bf16(float* d, const uint32_t* a,
                                         const uint32_t* b) {
    asm volatile(
        "mma.sync.aligned.m16n8k16.row.col.f32.bf16.bf16.f32 "
        "{%0,%1,%2,%3}, {%4,%5,%6,%7}, {%8,%9}, {%0,%1,%2,%3};"
        : "+f"(d[0]), "+f"(d[1]), "+f"(d[2]), "+f"(d[3])
        : "r"(a[0]), "r"(a[1]), "r"(a[2]), "r"(a[3]), "r"(b[0]), "r"(b[1]));
}

__device__ __forceinline__ uint32_t bf2_hi(float x, float y) {
    __nv_bfloat162 h = __floats2bfloat162_rn(x, y);
    return *(uint32_t*)&h;
}

template <int MODE>
__global__ __launch_bounds__(256) void gemm_kernel(
    const float* __restrict__ selfA,   // MODE 1: x
    const float* __restrict__ Wa,      // W_l (or Wd)
    const float* __restrict__ Wb,      // W_r (MODE 1/2)
    const float* __restrict__ bias,
    const float* __restrict__ xres,    // MODE 3
    const float* __restrict__ alpha_p, // MODE 3
    float* __restrict__ out_ext,       // MODE 3
    int n)
{
    __shared__ __nv_bfloat16 Ahi[BM][ASTR];
    __shared__ __nv_bfloat16 Alo[BM][ASTR];
    __shared__ __nv_bfloat16 Bhi[128][ASTR];
    __shared__ __nv_bfloat16 Blo[128][ASTR];
    __shared__ float s_bias[128];

    int t = threadIdx.x;
    int lane = t & 31;
    int w = t >> 5;
    int wm = w >> 2;          // 0..1, warp M-tile = 64 rows
    int wn = w & 3;           // 0..3
    int block_row = blockIdx.x * BM;

    if (t < 128) s_bias[t] = bias[t];

    float acc[4][4][4];
    #pragma unroll
    for (int mi = 0; mi < 4; mi++)
        #pragma unroll
        for (int nj = 0; nj < 4; nj++)
            #pragma unroll
            for (int q = 0; q < 4; q++) acc[mi][nj][q] = 0.f;

    const int NCH = (MODE == 3) ? 4 : 8;

    #pragma unroll 1
    for (int c = 0; c < NCH; c++) {
        const float* Asrc;
        const float* Bsrc;
        int kofs;
        if (MODE == 3) { Asrc = g_agg; Bsrc = Wa; kofs = c * KC; }
        else {
            kofs = (c & 3) * KC;
            Asrc = (c < 4) ? g_agg : ((MODE == 1) ? selfA : g_h1);
            Bsrc = (c < 4) ? Wa : Wb;
        }
        __syncthreads();   // previous chunk's mma reads done before restage

        // ---- stage A: 128 rows x 32 k, fp32 -> bf16 hi/lo (16 f/thread) ----
        {
            int row = t >> 1;            // 0..127
            int ks = (t & 1) * 16;       // 0,16
            int grow = block_row + row;
            float4 v0 = make_float4(0.f, 0.f, 0.f, 0.f);
            float4 v1 = v0, v2 = v0, v3 = v0;
            if (grow < n) {
                const float* p = Asrc + (size_t)grow * CH + kofs + ks;
                v0 = *(const float4*)p;
                v1 = *(const float4*)(p + 4);
                v2 = *(const float4*)(p + 8);
                v3 = *(const float4*)(p + 12);
            }
            uint4 hiA, loA, hiB, loB;
            hiA.x = bf2_hi(v0.x, v0.y);  hiA.y = bf2_hi(v0.z, v0.w);
            hiA.z = bf2_hi(v1.x, v1.y);  hiA.w = bf2_hi(v1.z, v1.w);
            hiB.x = bf2_hi(v2.x, v2.y);  hiB.y = bf2_hi(v2.z, v2.w);
            hiB.z = bf2_hi(v3.x, v3.y);  hiB.w = bf2_hi(v3.z, v3.w);
            float2 f;
            f = __bfloat1622float2(*(__nv_bfloat162*)&hiA.x);
            loA.x = bf2_hi(v0.x - f.x, v0.y - f.y);
            f = __bfloat1622float2(*(__nv_bfloat162*)&hiA.y);
            loA.y = bf2_hi(v0.z - f.x, v0.w - f.y);
            f = __bfloat1622float2(*(__nv_bfloat162*)&hiA.z);
            loA.z = bf2_hi(v1.x - f.x, v1.y - f.y);
            f = __bfloat1622float2(*(__nv_bfloat162*)&hiA.w);
            loA.w = bf2_hi(v1.z - f.x, v1.w - f.y);
            f = __bfloat1622float2(*(__nv_bfloat162*)&hiB.x);
            loB.x = bf2_hi(v2.x - f.x, v2.y - f.y);
            f = __bfloat1622float2(*(__nv_bfloat162*)&hiB.y);
            loB.y = bf2_hi(v2.z - f.x, v2.w - f.y);
            f = __bfloat1622float2(*(__nv_bfloat162*)&hiB.z);
            loB.z = bf2_hi(v3.x - f.x, v3.y - f.y);
            f = __bfloat1622float2(*(__nv_bfloat162*)&hiB.w);
            loB.w = bf2_hi(v3.z - f.x, v3.w - f.y);
            *(uint4*)&Ahi[row][ks]     = hiA;
            *(uint4*)&Ahi[row][ks + 8] = hiB;
            *(uint4*)&Alo[row][ks]     = loA;
            *(uint4*)&Alo[row][ks + 8] = loB;
        }

        // ---- stage B (transposed): Bs[n][k] = W[kofs+k][n], hi/lo ----
        {
            int nn = t >> 1;             // 0..127
            int ks = (t & 1) * 16;       // 0,16
            uint32_t hw[8], lw[8];
            #pragma unroll
            for (int j = 0; j < 8; j++) {
                float va = Bsrc[(size_t)(kofs + ks + 2 * j) * CH + nn];
                float vb = Bsrc[(size_t)(kofs + ks + 2 * j + 1) * CH + nn];
                hw[j] = bf2_hi(va, vb);
                float2 hf = __bfloat1622float2(*(__nv_bfloat162*)&hw[j]);
                lw[j] = bf2_hi(va - hf.x, vb - hf.y);
            }
            *(uint4*)&Bhi[nn][ks]     = make_uint4(hw[0], hw[1], hw[2], hw[3]);
            *(uint4*)&Bhi[nn][ks + 8] = make_uint4(hw[4], hw[5], hw[6], hw[7]);
            *(uint4*)&Blo[nn][ks]     = make_uint4(lw[0], lw[1], lw[2], lw[3]);
            *(uint4*)&Blo[nn][ks + 8] = make_uint4(lw[4], lw[5], lw[6], lw[7]);
        }
        __syncthreads();

        // ---- mma: 2 k16-steps, 3 passes each, 4 M-frags ----
        #pragma unroll
        for (int kk = 0; kk < KC; kk += 16) {
            int kw = kk + (lane & 3) * 2;
            int rr = wm * 64 + (lane >> 2);
            uint32_t b_hi[4][2], b_lo[4][2];
            #pragma unroll
            for (int nj = 0; nj < 4; nj++) {
                int cn = wn * 32 + nj * 8 + (lane >> 2);
                b_hi[nj][0] = *(uint32_t*)&Bhi[cn][kw];
                b_hi[nj][1] = *(uint32_t*)&Bhi[cn][kw + 8];
                b_lo[nj][0] = *(uint32_t*)&Blo[cn][kw];
                b_lo[nj][1] = *(uint32_t*)&Blo[cn][kw + 8];
            }
            #pragma unroll
            for (int mi = 0; mi < 4; mi++) {
                int r = rr + mi * 16;
                uint32_t a_hi[4], a_lo[4];
                a_hi[0] = *(uint32_t*)&Ahi[r][kw];
                a_hi[1] = *(uint32_t*)&Ahi[r + 8][kw];
                a_hi[2] = *(uint32_t*)&Ahi[r][kw + 8];
                a_hi[3] = *(uint32_t*)&Ahi[r + 8][kw + 8];
                a_lo[0] = *(uint32_t*)&Alo[r][kw];
                a_lo[1] = *(uint32_t*)&Alo[r + 8][kw];
                a_lo[2] = *(uint32_t*)&Alo[r][kw + 8];
                a_lo[3] = *(uint32_t*)&Alo[r + 8][kw + 8];
                #pragma unroll
                for (int nj = 0; nj < 4; nj++) {
                    mma_bf16(acc[mi][nj], a_hi, b_hi[nj]);
                    mma_bf16(acc[mi][nj], a_hi, b_lo[nj]);
                    mma_bf16(acc[mi][nj], a_lo, b_hi[nj]);
                }
            }
        }
    }

    // ---- epilogue ----
    float alpha = 0.f, one_m = 0.f;
    if (MODE == 3) { alpha = *alpha_p; one_m = 1.0f - alpha; }
    float* outp = (MODE == 1) ? g_h1 : ((MODE == 2) ? g_agg : out_ext);

    #pragma unroll
    for (int mi = 0; mi < 4; mi++) {
        #pragma unroll
        for (int part = 0; part < 2; part++) {
            int grow = block_row + wm * 64 + mi * 16 + part * 8 + (lane >> 2);
            if (grow < n) {
                #pragma unroll
                for (int nj = 0; nj < 4; nj++) {
                    int gcol = wn * 32 + nj * 8 + (lane & 3) * 2;
                    float v0 = acc[mi][nj][part * 2 + 0] + s_bias[gcol];
                    float v1 = acc[mi][nj][part * 2 + 1] + s_bias[gcol + 1];
                    float2 o;
                    if (MODE == 3) {
                        float2 xv = *(const float2*)(xres + (size_t)grow * CH + gcol);
                        o.x = alpha * v0 + one_m * xv.x;
                        o.y = alpha * v1 + one_m * xv.y;
                    } else {
                        o.x = fmaxf(v0, 0.f);
                        o.y = fmaxf(v1, 0.f);
                    }
                    *(float2*)(outp + (size_t)grow * CH + gcol) = o;
                }
            }
        }
    }
}

// ---------------------------------------------------------------------------
extern "C" void kernel_launch(void* const* d_in, const int* in_sizes, int n_in,
                              void* d_out, int out_size) {
    const float* x     = (const float*)d_in[0];
    const void*  edge  = d_in[1];
    const float* W1_l  = (const float*)d_in[2];
    const float* b1    = (const float*)d_in[3];
    const float* W1_r  = (const float*)d_in[4];
    const float* W2_l  = (const float*)d_in[5];
    const float* b2    = (const float*)d_in[6];
    const float* W2_r  = (const float*)d_in[7];
    const float* Wd    = (const float*)d_in[8];
    const float* bd    = (const float*)d_in[9];
    const float* alpha = (const float*)d_in[10];
    float* out = (float*)d_out;

    int n = in_sizes[0] / CH;            // 50000
    int E = in_sizes[1] / 2;             // 640000
    if (E > EMAX) E = EMAX;

    int eb = (E + 255) / 256;
    int nb = (n + 255) / 256;
    int sb = (n + 1023) / 1024;
    int ab = (n * 32 + 255) / 256;
    int gb = (n + BM - 1) / BM;          // 391

    // CSR build (once, serves both layers)
    detect_kernel<<<1, 256>>>((const unsigned*)edge);
    clear_cnt_kernel<<<nb, 256>>>(n);
    hist_kernel<<<eb, 256>>>(edge, E, n);
    scan1_kernel<<<sb, 1024>>>(n);
    scan2_kernel<<<1, 64>>>(sb);
    scan3_kernel<<<sb, 1024>>>(n, E);
    fill_kernel<<<eb, 256>>>(edge, E, n);

    // Layer 1
    aggregate_kernel<0><<<ab, 256>>>(x, n);
    gemm_kernel<1><<<gb, 256>>>(x, W1_l, W1_r, b1,
                                nullptr, nullptr, nullptr, n);
    // Layer 2
    aggregate_kernel<1><<<ab, 256>>>(nullptr, n);
    gemm_kernel<2><<<gb, 256>>>(nullptr, W2_l, W2_r, b2,
                                nullptr, nullptr, nullptr, n);
    // Decoder + residual
    gemm_kernel<3><<<gb, 256>>>(nullptr, Wd, nullptr, bd,
                                x, alpha, out, n);
}

// round 14
// speedup vs baseline: 1.3422x; 1.1343x over previous
#include <cuda_runtime.h>
#include <cuda_fp16.h>
#include <cstdint>

#define N_NODES 50000
#define EMAX    1000000
#define CH      128

// Scratch (device globals -- no allocation allowed)
__device__ __align__(16) float g_agg[(size_t)N_NODES * CH];
__device__ __align__(16) float g_h1[(size_t)N_NODES * CH];
__device__ int g_cnt[N_NODES];
__device__ int g_row[N_NODES + 1];
__device__ int g_cursor[N_NODES];
__device__ int g_bsum[64];
__device__ int g_boff[64];
__device__ int g_col[EMAX];
__device__ int g_is64;

// ---------------------------------------------------------------------------
// edge index read (int32 vs int64 runtime-detected)
// ---------------------------------------------------------------------------
__device__ __forceinline__ int edge_at(const void* e, int i) {
    return g_is64 ? (int)((const long long*)e)[i] : ((const int*)e)[i];
}

__global__ void detect_kernel(const unsigned* __restrict__ e) {
    __shared__ unsigned red[256];
    unsigned acc = 0;
    int t = threadIdx.x;
    #pragma unroll
    for (int j = 0; j < 8; j++) acc |= e[(t * 8 + j) * 2 + 1];
    red[t] = acc;
    __syncthreads();
    for (int s = 128; s > 0; s >>= 1) {
        if (t < s) red[t] |= red[t + s];
        __syncthreads();
    }
    if (t == 0) g_is64 = (red[0] == 0) ? 1 : 0;
}

// ---------------------------------------------------------------------------
// CSR build: histogram -> scan -> fill (proven R11)
// ---------------------------------------------------------------------------
__global__ void clear_cnt_kernel(int n) {
    int i = blockIdx.x * blockDim.x + threadIdx.x;
    if (i < n) g_cnt[i] = 0;
}

__global__ void hist_kernel(const void* __restrict__ edge, int E, int n) {
    int i = blockIdx.x * blockDim.x + threadIdx.x;
    if (i >= E) return;
    int d = edge_at(edge, E + i);
    if ((unsigned)d < (unsigned)n) atomicAdd(&g_cnt[d], 1);
}

__global__ void scan1_kernel(int n) {
    __shared__ int sh[1024];
    int t = threadIdx.x;
    int idx = blockIdx.x * 1024 + t;
    int v = (idx < n) ? g_cnt[idx] : 0;
    sh[t] = v;
    __syncthreads();
    #pragma unroll
    for (int off = 1; off < 1024; off <<= 1) {
        int add = (t >= off) ? sh[t - off] : 0;
        __syncthreads();
        sh[t] += add;
        __syncthreads();
    }
    if (idx < n) g_row[idx] = sh[t] - v;
    if (t == 1023) g_bsum[blockIdx.x] = sh[1023];
}

__global__ void scan2_kernel(int nb) {
    __shared__ int sh[64];
    int t = threadIdx.x;
    sh[t] = (t < nb) ? g_bsum[t] : 0;
    __syncthreads();
    if (t == 0) {
        int run = 0;
        for (int i = 0; i < nb; i++) {
            g_boff[i] = run;
            run += sh[i];
        }
    }
}

__global__ void scan3_kernel(int n, int E) {
    int idx = blockIdx.x * 1024 + threadIdx.x;
    if (idx < n) {
        g_row[idx] += g_boff[blockIdx.x];
        g_cursor[idx] = 0;
    }
    if (idx == 0) g_row[n] = E;
}

__global__ void fill_kernel(const void* __restrict__ edge, int E, int n) {
    int i = blockIdx.x * blockDim.x + threadIdx.x;
    if (i >= E) return;
    int s = edge_at(edge, i);
    int d = edge_at(edge, E + i);
    if ((unsigned)d >= (unsigned)n) return;
    if ((unsigned)s >= (unsigned)n) s = 0;
    int pos = g_row[d] + atomicAdd(&g_cursor[d], 1);
    g_col[pos] = s;
}

// ---------------------------------------------------------------------------
// aggregate: one warp per destination row, pure gather, mean folded in.
// SRC 0: feat = x (param). SRC 1: feat = g_h1. Output: g_agg (pre-scaled).
// ---------------------------------------------------------------------------
template <int SRC>
__global__ void aggregate_kernel(const float* __restrict__ feat_ext, int n) {
    int row = (blockIdx.x * blockDim.x + threadIdx.x) >> 5;
    int lane = threadIdx.x & 31;
    if (row >= n) return;

    const float* __restrict__ feat = (SRC == 0) ? feat_ext : g_h1;

    int base = g_row[row];
    int end  = g_row[row + 1];
    int deg  = end - base;

    float a0 = 0.f, a1 = 0.f, a2 = 0.f, a3 = 0.f;
    int j = base;
    for (; j + 3 < end; j += 4) {
        int s0 = g_col[j],     s1 = g_col[j + 1];
        int s2 = g_col[j + 2], s3 = g_col[j + 3];
        float4 v0 = *(const float4*)(feat + (size_t)s0 * CH + lane * 4);
        float4 v1 = *(const float4*)(feat + (size_t)s1 * CH + lane * 4);
        float4 v2 = *(const float4*)(feat + (size_t)s2 * CH + lane * 4);
        float4 v3 = *(const float4*)(feat + (size_t)s3 * CH + lane * 4);
        a0 += (v0.x + v1.x) + (v2.x + v3.x);
        a1 += (v0.y + v1.y) + (v2.y + v3.y);
        a2 += (v0.z + v1.z) + (v2.z + v3.z);
        a3 += (v0.w + v1.w) + (v2.w + v3.w);
    }
    for (; j < end; j++) {
        int s0 = g_col[j];
        float4 v0 = *(const float4*)(feat + (size_t)s0 * CH + lane * 4);
        a0 += v0.x; a1 += v0.y; a2 += v0.z; a3 += v0.w;
    }

    float sc = 1.0f / fmaxf((float)deg, 1.0f);
    float4 o = make_float4(a0 * sc, a1 * sc, a2 * sc, a3 * sc);
    *(float4*)(g_agg + (size_t)row * CH + lane * 4) = o;
}

// ---------------------------------------------------------------------------
// GEMM via mma.sync m16n8k16 fp16 (HMMA), fp16x2 split on A (2 passes):
//   D = Ah*Bh + Al*Bh,  A = Ah + Al exact to ~2^-22, B = Bh (fp16 rounded).
// Dropped error: A*(B - Bh) ~ 2^-11 relative -> measured rel_err ~1e-4.
// BM=64, BN=128, KC=32. 8 warps in 2(M) x 4(N); warp tile 32x32.
// g_agg is pre-scaled by 1/deg (mean folded into aggregate).
// MODE 1: relu( [agg | x ] @ [W1_l;W1_r] + b1 ) -> g_h1     (K=256)
// MODE 2: relu( [agg | h1] @ [W2_l;W2_r] + b2 ) -> g_agg (h2)
// MODE 3: alpha*(g_agg @ Wd + bd) + (1-alpha)*xres -> out_ext (K=128)
// ---------------------------------------------------------------------------
#define BM 64
#define KC 32
#define ASTR 40   // fp16 row stride: 20 words -> conflict-free frag loads

__device__ __forceinline__ void mma_f16(float* d, const uint32_t* a,
                                        const uint32_t* b) {
    asm volatile(
        "mma.sync.aligned.m16n8k16.row.col.f32.f16.f16.f32 "
        "{%0,%1,%2,%3}, {%4,%5,%6,%7}, {%8,%9}, {%0,%1,%2,%3};"
        : "+f"(d[0]), "+f"(d[1]), "+f"(d[2]), "+f"(d[3])
        : "r"(a[0]), "r"(a[1]), "r"(a[2]), "r"(a[3]), "r"(b[0]), "r"(b[1]));
}

__device__ __forceinline__ uint32_t h2pack(float x, float y) {
    __half2 h = __floats2half2_rn(x, y);
    return *(uint32_t*)&h;
}

template <int MODE>
__global__ __launch_bounds__(256) void gemm_kernel(
    const float* __restrict__ selfA,   // MODE 1: x
    const float* __restrict__ Wa,      // W_l (or Wd)
    const float* __restrict__ Wb,      // W_r (MODE 1/2)
    const float* __restrict__ bias,
    const float* __restrict__ xres,    // MODE 3
    const float* __restrict__ alpha_p, // MODE 3
    float* __restrict__ out_ext,       // MODE 3
    int n)
{
    __shared__ __half Ahi[BM][ASTR];
    __shared__ __half Alo[BM][ASTR];
    __shared__ __half Bs[128][ASTR];
    __shared__ float s_bias[128];

    int t = threadIdx.x;
    int lane = t & 31;
    int w = t >> 5;
    int wm = w >> 2;
    int wn = w & 3;
    int block_row = blockIdx.x * BM;

    if (t < 128) s_bias[t] = bias[t];

    float acc[2][4][4];
    #pragma unroll
    for (int mi = 0; mi < 2; mi++)
        #pragma unroll
        for (int nj = 0; nj < 4; nj++)
            #pragma unroll
            for (int q = 0; q < 4; q++) acc[mi][nj][q] = 0.f;

    const int NCH = (MODE == 3) ? 4 : 8;

    #pragma unroll 1
    for (int c = 0; c < NCH; c++) {
        const float* Asrc;
        const float* Bsrc;
        int kofs;
        if (MODE == 3) { Asrc = g_agg; Bsrc = Wa; kofs = c * KC; }
        else {
            kofs = (c & 3) * KC;
            Asrc = (c < 4) ? g_agg : ((MODE == 1) ? selfA : g_h1);
            Bsrc = (c < 4) ? Wa : Wb;
        }
        __syncthreads();   // previous chunk's mma reads done before restage

        // ---- stage A: 64 rows x 32 k, fp32 -> fp16 hi/lo ----
        {
            int row = t >> 2;            // 0..63
            int ks = (t & 3) * 8;        // 0,8,16,24
            int grow = block_row + row;
            float4 v0 = make_float4(0.f, 0.f, 0.f, 0.f);
            float4 v1 = v0;
            if (grow < n) {
                const float* p = Asrc + (size_t)grow * CH + kofs + ks;
                v0 = *(const float4*)p;
                v1 = *(const float4*)(p + 4);
            }
            uint4 hi, lo;
            hi.x = h2pack(v0.x, v0.y);  hi.y = h2pack(v0.z, v0.w);
            hi.z = h2pack(v1.x, v1.y);  hi.w = h2pack(v1.z, v1.w);
            float2 f0 = __half22float2(*(__half2*)&hi.x);
            float2 f1 = __half22float2(*(__half2*)&hi.y);
            float2 f2 = __half22float2(*(__half2*)&hi.z);
            float2 f3 = __half22float2(*(__half2*)&hi.w);
            lo.x = h2pack(v0.x - f0.x, v0.y - f0.y);
            lo.y = h2pack(v0.z - f1.x, v0.w - f1.y);
            lo.z = h2pack(v1.x - f2.x, v1.y - f2.y);
            lo.w = h2pack(v1.z - f3.x, v1.w - f3.y);
            *(uint4*)&Ahi[row][ks] = hi;
            *(uint4*)&Alo[row][ks] = lo;
        }

        // ---- stage B (transposed): Bs[n][k] = W[kofs+k][n], single fp16 ----
        {
            int nn = t >> 1;             // 0..127
            int ks = (t & 1) * 16;       // 0,16
            uint32_t hw[8];
            #pragma unroll
            for (int j = 0; j < 8; j++) {
                float va = Bsrc[(size_t)(kofs + ks + 2 * j) * CH + nn];
                float vb = Bsrc[(size_t)(kofs + ks + 2 * j + 1) * CH + nn];
                hw[j] = h2pack(va, vb);
            }
            *(uint4*)&Bs[nn][ks]     = make_uint4(hw[0], hw[1], hw[2], hw[3]);
            *(uint4*)&Bs[nn][ks + 8] = make_uint4(hw[4], hw[5], hw[6], hw[7]);
        }
        __syncthreads();

        // ---- mma: 2 k16-steps, 2 passes each ----
        #pragma unroll
        for (int kk = 0; kk < KC; kk += 16) {
            int kw = kk + (lane & 3) * 2;
            int rr = wm * 32 + (lane >> 2);
            uint32_t a_hi[2][4], a_lo[2][4], b_f[4][2];
            #pragma unroll
            for (int mi = 0; mi < 2; mi++) {
                int r = rr + mi * 16;
                a_hi[mi][0] = *(uint32_t*)&Ahi[r][kw];
                a_hi[mi][1] = *(uint32_t*)&Ahi[r + 8][kw];
                a_hi[mi][2] = *(uint32_t*)&Ahi[r][kw + 8];
                a_hi[mi][3] = *(uint32_t*)&Ahi[r + 8][kw + 8];
                a_lo[mi][0] = *(uint32_t*)&Alo[r][kw];
                a_lo[mi][1] = *(uint32_t*)&Alo[r + 8][kw];
                a_lo[mi][2] = *(uint32_t*)&Alo[r][kw + 8];
                a_lo[mi][3] = *(uint32_t*)&Alo[r + 8][kw + 8];
            }
            #pragma unroll
            for (int nj = 0; nj < 4; nj++) {
                int cn = wn * 32 + nj * 8 + (lane >> 2);
                b_f[nj][0] = *(uint32_t*)&Bs[cn][kw];
                b_f[nj][1] = *(uint32_t*)&Bs[cn][kw + 8];
            }
            #pragma unroll
            for (int mi = 0; mi < 2; mi++)
                #pragma unroll
                for (int nj = 0; nj < 4; nj++) {
                    mma_f16(acc[mi][nj], a_hi[mi], b_f[nj]);
                    mma_f16(acc[mi][nj], a_lo[mi], b_f[nj]);
                }
        }
    }

    // ---- epilogue ----
    float alpha = 0.f, one_m = 0.f;
    if (MODE == 3) { alpha = *alpha_p; one_m = 1.0f - alpha; }
    float* outp = (MODE == 1) ? g_h1 : ((MODE == 2) ? g_agg : out_ext);

    #pragma unroll
    for (int mi = 0; mi < 2; mi++) {
        #pragma unroll
        for (int part = 0; part < 2; part++) {
            int grow = block_row + wm * 32 + mi * 16 + part * 8 + (lane >> 2);
            if (grow < n) {
                #pragma unroll
                for (int nj = 0; nj < 4; nj++) {
                    int gcol = wn * 32 + nj * 8 + (lane & 3) * 2;
                    float v0 = acc[mi][nj][part * 2 + 0] + s_bias[gcol];
                    float v1 = acc[mi][nj][part * 2 + 1] + s_bias[gcol + 1];
                    float2 o;
                    if (MODE == 3) {
                        float2 xv = *(const float2*)(xres + (size_t)grow * CH + gcol);
                        o.x = alpha * v0 + one_m * xv.x;
                        o.y = alpha * v1 + one_m * xv.y;
                    } else {
                        o.x = fmaxf(v0, 0.f);
                        o.y = fmaxf(v1, 0.f);
                    }
                    *(float2*)(outp + (size_t)grow * CH + gcol) = o;
                }
            }
        }
    }
}

// ---------------------------------------------------------------------------
extern "C" void kernel_launch(void* const* d_in, const int* in_sizes, int n_in,
                              void* d_out, int out_size) {
    const float* x     = (const float*)d_in[0];
    const void*  edge  = d_in[1];
    const float* W1_l  = (const float*)d_in[2];
    const float* b1    = (const float*)d_in[3];
    const float* W1_r  = (const float*)d_in[4];
    const float* W2_l  = (const float*)d_in[5];
    const float* b2    = (const float*)d_in[6];
    const float* W2_r  = (const float*)d_in[7];
    const float* Wd    = (const float*)d_in[8];
    const float* bd    = (const float*)d_in[9];
    const float* alpha = (const float*)d_in[10];
    float* out = (float*)d_out;

    int n = in_sizes[0] / CH;            // 50000
    int E = in_sizes[1] / 2;             // 640000
    if (E > EMAX) E = EMAX;

    int eb = (E + 255) / 256;
    int nb = (n + 255) / 256;
    int sb = (n + 1023) / 1024;
    int ab = (n * 32 + 255) / 256;
    int gb = (n + BM - 1) / BM;          // 782

    // CSR build (once, serves both layers)
    detect_kernel<<<1, 256>>>((const unsigned*)edge);
    clear_cnt_kernel<<<nb, 256>>>(n);
    hist_kernel<<<eb, 256>>>(edge, E, n);
    scan1_kernel<<<sb, 1024>>>(n);
    scan2_kernel<<<1, 64>>>(sb);
    scan3_kernel<<<sb, 1024>>>(n, E);
    fill_kernel<<<eb, 256>>>(edge, E, n);

    // Layer 1
    aggregate_kernel<0><<<ab, 256>>>(x, n);
    gemm_kernel<1><<<gb, 256>>>(x, W1_l, W1_r, b1,
                                nullptr, nullptr, nullptr, n);
    // Layer 2
    aggregate_kernel<1><<<ab, 256>>>(nullptr, n);
    gemm_kernel<2><<<gb, 256>>>(nullptr, W2_l, W2_r, b2,
                                nullptr, nullptr, nullptr, n);
    // Decoder + residual
    gemm_kernel<3><<<gb, 256>>>(nullptr, Wd, nullptr, bd,
                                x, alpha, out, n);
}

// round 15
// speedup vs baseline: 1.5359x; 1.1443x over previous
#include <cuda_runtime.h>
#include <cuda_fp16.h>
#include <cstdint>

#define N_NODES 50000
#define EMAX    1000000
#define CH      128

// Scratch (device globals -- no allocation allowed)
__device__ __align__(16) __half g_xh[(size_t)N_NODES * CH];   // x fp16, later h2
__device__ __align__(16) __half g_h1h[(size_t)N_NODES * CH];  // h1 fp16
__device__ __align__(16) __half g_aggh[(size_t)N_NODES * CH]; // mean-agg fp16
__device__ int g_cnt[N_NODES];
__device__ int g_row[N_NODES + 1];
__device__ int g_cursor[N_NODES];
__device__ int g_bsum[64];
__device__ int g_boff[64];
__device__ int g_col[EMAX];
__device__ int g_is64;

__device__ __forceinline__ uint32_t h2pack(float x, float y) {
    __half2 h = __floats2half2_rn(x, y);
    return *(uint32_t*)&h;
}

// ---------------------------------------------------------------------------
// edge index read (int32 vs int64 runtime-detected)
// ---------------------------------------------------------------------------
__device__ __forceinline__ int edge_at(const void* e, int i) {
    return g_is64 ? (int)((const long long*)e)[i] : ((const int*)e)[i];
}

__global__ void detect_kernel(const unsigned* __restrict__ e) {
    __shared__ unsigned red[256];
    unsigned acc = 0;
    int t = threadIdx.x;
    #pragma unroll
    for (int j = 0; j < 8; j++) acc |= e[(t * 8 + j) * 2 + 1];
    red[t] = acc;
    __syncthreads();
    for (int s = 128; s > 0; s >>= 1) {
        if (t < s) red[t] |= red[t + s];
        __syncthreads();
    }
    if (t == 0) g_is64 = (red[0] == 0) ? 1 : 0;
}

// ---------------------------------------------------------------------------
// convert x -> fp16 once (8 floats / thread)
// ---------------------------------------------------------------------------
__global__ void convert_x_kernel(const float* __restrict__ x, int n) {
    int i = blockIdx.x * blockDim.x + threadIdx.x;
    int total = n * CH / 8;
    if (i >= total) return;
    const float4* p = (const float4*)x + (size_t)i * 2;
    float4 v0 = p[0], v1 = p[1];
    uint4 o;
    o.x = h2pack(v0.x, v0.y);  o.y = h2pack(v0.z, v0.w);
    o.z = h2pack(v1.x, v1.y);  o.w = h2pack(v1.z, v1.w);
    *((uint4*)g_xh + i) = o;
}

// ---------------------------------------------------------------------------
// CSR build: histogram -> scan -> fill (proven R11)
// ---------------------------------------------------------------------------
__global__ void clear_cnt_kernel(int n) {
    int i = blockIdx.x * blockDim.x + threadIdx.x;
    if (i < n) g_cnt[i] = 0;
}

__global__ void hist_kernel(const void* __restrict__ edge, int E, int n) {
    int i = blockIdx.x * blockDim.x + threadIdx.x;
    if (i >= E) return;
    int d = edge_at(edge, E + i);
    if ((unsigned)d < (unsigned)n) atomicAdd(&g_cnt[d], 1);
}

__global__ void scan1_kernel(int n) {
    __shared__ int sh[1024];
    int t = threadIdx.x;
    int idx = blockIdx.x * 1024 + t;
    int v = (idx < n) ? g_cnt[idx] : 0;
    sh[t] = v;
    __syncthreads();
    #pragma unroll
    for (int off = 1; off < 1024; off <<= 1) {
        int add = (t >= off) ? sh[t - off] : 0;
        __syncthreads();
        sh[t] += add;
        __syncthreads();
    }
    if (idx < n) g_row[idx] = sh[t] - v;
    if (t == 1023) g_bsum[blockIdx.x] = sh[1023];
}

__global__ void scan2_kernel(int nb) {
    __shared__ int sh[64];
    int t = threadIdx.x;
    sh[t] = (t < nb) ? g_bsum[t] : 0;
    __syncthreads();
    if (t == 0) {
        int run = 0;
        for (int i = 0; i < nb; i++) {
            g_boff[i] = run;
            run += sh[i];
        }
    }
}

__global__ void scan3_kernel(int n, int E) {
    int idx = blockIdx.x * 1024 + threadIdx.x;
    if (idx < n) {
        g_row[idx] += g_boff[blockIdx.x];
        g_cursor[idx] = 0;
    }
    if (idx == 0) g_row[n] = E;
}

__global__ void fill_kernel(const void* __restrict__ edge, int E, int n) {
    int i = blockIdx.x * blockDim.x + threadIdx.x;
    if (i >= E) return;
    int s = edge_at(edge, i);
    int d = edge_at(edge, E + i);
    if ((unsigned)d >= (unsigned)n) return;
    if ((unsigned)s >= (unsigned)n) s = 0;
    int pos = g_row[d] + atomicAdd(&g_cursor[d], 1);
    g_col[pos] = s;
}

// ---------------------------------------------------------------------------
// aggregate: one warp per destination row, fp16 gather (4 halves/lane),
// fp32 accumulate, mean folded in, fp16 output.
// SRC 0: feat = g_xh. SRC 1: feat = g_h1h. Output: g_aggh.
// ---------------------------------------------------------------------------
template <int SRC>
__global__ void aggregate_kernel(int n) {
    int row = (blockIdx.x * blockDim.x + threadIdx.x) >> 5;
    int lane = threadIdx.x & 31;
    if (row >= n) return;

    const __half* __restrict__ feat = (SRC == 0) ? g_xh : g_h1h;

    int base = g_row[row];
    int end  = g_row[row + 1];
    int deg  = end - base;

    float a0 = 0.f, a1 = 0.f, a2 = 0.f, a3 = 0.f;
    int j = base;
    for (; j + 3 < end; j += 4) {
        int s0 = g_col[j],     s1 = g_col[j + 1];
        int s2 = g_col[j + 2], s3 = g_col[j + 3];
        uint2 u0 = *(const uint2*)(feat + (size_t)s0 * CH + lane * 4);
        uint2 u1 = *(const uint2*)(feat + (size_t)s1 * CH + lane * 4);
        uint2 u2 = *(const uint2*)(feat + (size_t)s2 * CH + lane * 4);
        uint2 u3 = *(const uint2*)(feat + (size_t)s3 * CH + lane * 4);
        float2 f0a = __half22float2(*(__half2*)&u0.x), f0b = __half22float2(*(__half2*)&u0.y);
        float2 f1a = __half22float2(*(__half2*)&u1.x), f1b = __half22float2(*(__half2*)&u1.y);
        float2 f2a = __half22float2(*(__half2*)&u2.x), f2b = __half22float2(*(__half2*)&u2.y);
        float2 f3a = __half22float2(*(__half2*)&u3.x), f3b = __half22float2(*(__half2*)&u3.y);
        a0 += (f0a.x + f1a.x) + (f2a.x + f3a.x);
        a1 += (f0a.y + f1a.y) + (f2a.y + f3a.y);
        a2 += (f0b.x + f1b.x) + (f2b.x + f3b.x);
        a3 += (f0b.y + f1b.y) + (f2b.y + f3b.y);
    }
    for (; j < end; j++) {
        int s0 = g_col[j];
        uint2 u0 = *(const uint2*)(feat + (size_t)s0 * CH + lane * 4);
        float2 fa = __half22float2(*(__half2*)&u0.x), fb = __half22float2(*(__half2*)&u0.y);
        a0 += fa.x; a1 += fa.y; a2 += fb.x; a3 += fb.y;
    }

    float sc = 1.0f / fmaxf((float)deg, 1.0f);
    uint2 o;
    o.x = h2pack(a0 * sc, a1 * sc);
    o.y = h2pack(a2 * sc, a3 * sc);
    *(uint2*)(g_aggh + (size_t)row * CH + lane * 4) = o;
}

// ---------------------------------------------------------------------------
// GEMM via mma.sync m16n8k16 fp16 (HMMA), SINGLE pass (A,B both fp16).
// A operands pre-stored fp16 (pure copies); B converted fp32->fp16 per CTA.
// BM=64, BN=128, KC=32. 8 warps in 2(M) x 4(N); warp tile 32x32.
// MODE 1: relu( [agg | xh] @ [W1_l;W1_r] + b1 ) -> g_h1h   (K=256)
// MODE 2: relu( [agg | h1] @ [W2_l;W2_r] + b2 ) -> g_xh (h2)
// MODE 3: alpha*(h2 @ Wd + bd) + (1-alpha)*xres -> out_ext (K=128)
// ---------------------------------------------------------------------------
#define BM 64
#define KC 32
#define ASTR 40   // fp16 row stride: 20 words -> conflict-free frag loads

__device__ __forceinline__ void mma_f16(float* d, const uint32_t* a,
                                        const uint32_t* b) {
    asm volatile(
        "mma.sync.aligned.m16n8k16.row.col.f32.f16.f16.f32 "
        "{%0,%1,%2,%3}, {%4,%5,%6,%7}, {%8,%9}, {%0,%1,%2,%3};"
        : "+f"(d[0]), "+f"(d[1]), "+f"(d[2]), "+f"(d[3])
        : "r"(a[0]), "r"(a[1]), "r"(a[2]), "r"(a[3]), "r"(b[0]), "r"(b[1]));
}

template <int MODE>
__global__ __launch_bounds__(256) void gemm_kernel(
    const float* __restrict__ Wa,      // W_l (or Wd)
    const float* __restrict__ Wb,      // W_r (MODE 1/2)
    const float* __restrict__ bias,
    const float* __restrict__ xres,    // MODE 3
    const float* __restrict__ alpha_p, // MODE 3
    float* __restrict__ out_ext,       // MODE 3
    int n)
{
    __shared__ __half As[BM][ASTR];
    __shared__ __half Bs[128][ASTR];
    __shared__ float s_bias[128];

    int t = threadIdx.x;
    int lane = t & 31;
    int w = t >> 5;
    int wm = w >> 2;
    int wn = w & 3;
    int block_row = blockIdx.x * BM;

    if (t < 128) s_bias[t] = bias[t];

    float acc[2][4][4];
    #pragma unroll
    for (int mi = 0; mi < 2; mi++)
        #pragma unroll
        for (int nj = 0; nj < 4; nj++)
            #pragma unroll
            for (int q = 0; q < 4; q++) acc[mi][nj][q] = 0.f;

    const int NCH = (MODE == 3) ? 4 : 8;

    #pragma unroll 1
    for (int c = 0; c < NCH; c++) {
        const __half* Asrc;
        const float* Bsrc;
        int kofs;
        if (MODE == 3) { Asrc = g_xh; Bsrc = Wa; kofs = c * KC; }
        else {
            kofs = (c & 3) * KC;
            Asrc = (c < 4) ? g_aggh : ((MODE == 1) ? g_xh : g_h1h);
            Bsrc = (c < 4) ? Wa : Wb;
        }
        __syncthreads();   // previous chunk's mma reads done before restage

        // ---- stage A: pure fp16 copy, 64 rows x 32 k (8 halves/thread) ----
        {
            int row = t >> 2;            // 0..63
            int ks = (t & 3) * 8;        // 0,8,16,24
            int grow = block_row + row;
            uint4 v = make_uint4(0, 0, 0, 0);
            if (grow < n)
                v = *(const uint4*)(Asrc + (size_t)grow * CH + kofs + ks);
            *(uint4*)&As[row][ks] = v;
        }

        // ---- stage B (transposed): Bs[n][k] = W[kofs+k][n], fp32->fp16 ----
        {
            int nn = t >> 1;             // 0..127
            int ks = (t & 1) * 16;       // 0,16
            uint32_t hw[8];
            #pragma unroll
            for (int j = 0; j < 8; j++) {
                float va = Bsrc[(size_t)(kofs + ks + 2 * j) * CH + nn];
                float vb = Bsrc[(size_t)(kofs + ks + 2 * j + 1) * CH + nn];
                hw[j] = h2pack(va, vb);
            }
            *(uint4*)&Bs[nn][ks]     = make_uint4(hw[0], hw[1], hw[2], hw[3]);
            *(uint4*)&Bs[nn][ks + 8] = make_uint4(hw[4], hw[5], hw[6], hw[7]);
        }
        __syncthreads();

        // ---- mma: 2 k16-steps, single pass ----
        #pragma unroll
        for (int kk = 0; kk < KC; kk += 16) {
            int kw = kk + (lane & 3) * 2;
            int rr = wm * 32 + (lane >> 2);
            uint32_t a_f[2][4], b_f[4][2];
            #pragma unroll
            for (int mi = 0; mi < 2; mi++) {
                int r = rr + mi * 16;
                a_f[mi][0] = *(uint32_t*)&As[r][kw];
                a_f[mi][1] = *(uint32_t*)&As[r + 8][kw];
                a_f[mi][2] = *(uint32_t*)&As[r][kw + 8];
                a_f[mi][3] = *(uint32_t*)&As[r + 8][kw + 8];
            }
            #pragma unroll
            for (int nj = 0; nj < 4; nj++) {
                int cn = wn * 32 + nj * 8 + (lane >> 2);
                b_f[nj][0] = *(uint32_t*)&Bs[cn][kw];
                b_f[nj][1] = *(uint32_t*)&Bs[cn][kw + 8];
            }
            #pragma unroll
            for (int mi = 0; mi < 2; mi++)
                #pragma unroll
                for (int nj = 0; nj < 4; nj++)
                    mma_f16(acc[mi][nj], a_f[mi], b_f[nj]);
        }
    }

    // ---- epilogue ----
    float alpha = 0.f, one_m = 0.f;
    if (MODE == 3) { alpha = *alpha_p; one_m = 1.0f - alpha; }
    __half* outh = (MODE == 1) ? g_h1h : g_xh;

    #pragma unroll
    for (int mi = 0; mi < 2; mi++) {
        #pragma unroll
        for (int part = 0; part < 2; part++) {
            int grow = block_row + wm * 32 + mi * 16 + part * 8 + (lane >> 2);
            if (grow < n) {
                #pragma unroll
                for (int nj = 0; nj < 4; nj++) {
                    int gcol = wn * 32 + nj * 8 + (lane & 3) * 2;
                    float v0 = acc[mi][nj][part * 2 + 0] + s_bias[gcol];
                    float v1 = acc[mi][nj][part * 2 + 1] + s_bias[gcol + 1];
                    size_t o = (size_t)grow * CH + gcol;
                    if (MODE == 3) {
                        float2 xv = *(const float2*)(xres + o);
                        float2 ov;
                        ov.x = alpha * v0 + one_m * xv.x;
                        ov.y = alpha * v1 + one_m * xv.y;
                        *(float2*)(out_ext + o) = ov;
                    } else {
                        *(uint32_t*)(outh + o) =
                            h2pack(fmaxf(v0, 0.f), fmaxf(v1, 0.f));
                    }
                }
            }
        }
    }
}

// ---------------------------------------------------------------------------
extern "C" void kernel_launch(void* const* d_in, const int* in_sizes, int n_in,
                              void* d_out, int out_size) {
    const float* x     = (const float*)d_in[0];
    const void*  edge  = d_in[1];
    const float* W1_l  = (const float*)d_in[2];
    const float* b1    = (const float*)d_in[3];
    const float* W1_r  = (const float*)d_in[4];
    const float* W2_l  = (const float*)d_in[5];
    const float* b2    = (const float*)d_in[6];
    const float* W2_r  = (const float*)d_in[7];
    const float* Wd    = (const float*)d_in[8];
    const float* bd    = (const float*)d_in[9];
    const float* alpha = (const float*)d_in[10];
    float* out = (float*)d_out;

    int n = in_sizes[0] / CH;            // 50000
    int E = in_sizes[1] / 2;             // 640000
    if (E > EMAX) E = EMAX;

    int eb = (E + 255) / 256;
    int nb = (n + 255) / 256;
    int sb = (n + 1023) / 1024;
    int cb = (n * CH / 8 + 255) / 256;
    int ab = (n * 32 + 255) / 256;
    int gb = (n + BM - 1) / BM;          // 782

    // prep: dtype detect, x->fp16, CSR build (once)
    detect_kernel<<<1, 256>>>((const unsigned*)edge);
    convert_x_kernel<<<cb, 256>>>(x, n);
    clear_cnt_kernel<<<nb, 256>>>(n);
    hist_kernel<<<eb, 256>>>(edge, E, n);
    scan1_kernel<<<sb, 1024>>>(n);
    scan2_kernel<<<1, 64>>>(sb);
    scan3_kernel<<<sb, 1024>>>(n, E);
    fill_kernel<<<eb, 256>>>(edge, E, n);

    // Layer 1
    aggregate_kernel<0><<<ab, 256>>>(n);
    gemm_kernel<1><<<gb, 256>>>(W1_l, W1_r, b1, nullptr, nullptr, nullptr, n);
    // Layer 2
    aggregate_kernel<1><<<ab, 256>>>(n);
    gemm_kernel<2><<<gb, 256>>>(W2_l, W2_r, b2, nullptr, nullptr, nullptr, n);
    // Decoder + residual
    gemm_kernel<3><<<gb, 256>>>(Wd, nullptr, bd, x, alpha, out, n);
}

// round 16
// speedup vs baseline: 1.6436x; 1.0702x over previous
#include <cuda_runtime.h>
#include <cuda_fp16.h>
#include <cstdint>

#define N_NODES 50000
#define EMAX    1000000
#define CH      128

// Scratch (device globals -- no allocation allowed)
__device__ __align__(16) __half g_xh[(size_t)N_NODES * CH];   // x fp16
__device__ __align__(16) __half g_h1h[(size_t)N_NODES * CH];  // h1 fp16
__device__ __align__(16) __half g_aggh[(size_t)N_NODES * CH]; // mean-agg fp16
__device__ int g_cnt[N_NODES];
__device__ int g_row[N_NODES + 1];
__device__ int g_cursor[N_NODES];
__device__ int g_bsum[64];
__device__ int g_boff[64];
__device__ int g_col[EMAX];
__device__ int g_is64;

// pre-transposed fp16 weights: Wt[n][k], k contiguous
__device__ __align__(16) __half g_W1t[128 * 256];
__device__ __align__(16) __half g_W2t[128 * 256];
__device__ __align__(16) __half g_Wdt[128 * 128];

__device__ __forceinline__ uint32_t h2pack(float x, float y) {
    __half2 h = __floats2half2_rn(x, y);
    return *(uint32_t*)&h;
}

// ---------------------------------------------------------------------------
// edge index read (int32 vs int64 runtime-detected)
// ---------------------------------------------------------------------------
__device__ __forceinline__ int edge_at(const void* e, int i) {
    return g_is64 ? (int)((const long long*)e)[i] : ((const int*)e)[i];
}

__global__ void detect_kernel(const unsigned* __restrict__ e) {
    __shared__ unsigned red[256];
    unsigned acc = 0;
    int t = threadIdx.x;
    #pragma unroll
    for (int j = 0; j < 8; j++) acc |= e[(t * 8 + j) * 2 + 1];
    red[t] = acc;
    __syncthreads();
    for (int s = 128; s > 0; s >>= 1) {
        if (t < s) red[t] |= red[t + s];
        __syncthreads();
    }
    if (t == 0) g_is64 = (red[0] == 0) ? 1 : 0;
}

// ---------------------------------------------------------------------------
// convert x -> fp16 once (8 floats / thread)
// ---------------------------------------------------------------------------
__global__ void convert_x_kernel(const float* __restrict__ x, int n) {
    int i = blockIdx.x * blockDim.x + threadIdx.x;
    int total = n * CH / 8;
    if (i >= total) return;
    const float4* p = (const float4*)x + (size_t)i * 2;
    float4 v0 = p[0], v1 = p[1];
    uint4 o;
    o.x = h2pack(v0.x, v0.y);  o.y = h2pack(v0.z, v0.w);
    o.z = h2pack(v1.x, v1.y);  o.w = h2pack(v1.z, v1.w);
    *((uint4*)g_xh + i) = o;
}

// ---------------------------------------------------------------------------
// prep_w: transpose + fp16-convert all weights once (81920 elements)
// ---------------------------------------------------------------------------
__global__ void prep_w_kernel(const float* __restrict__ W1l,
                              const float* __restrict__ W1r,
                              const float* __restrict__ W2l,
                              const float* __restrict__ W2r,
                              const float* __restrict__ Wd) {
    int idx = blockIdx.x * blockDim.x + threadIdx.x;
    if (idx < 32768) {
        int nn = idx >> 8, k = idx & 255;
        float v = (k < 128) ? W1l[(size_t)k * CH + nn]
                            : W1r[(size_t)(k - 128) * CH + nn];
        g_W1t[nn * 256 + k] = __float2half(v);
    } else if (idx < 65536) {
        int r = idx - 32768;
        int nn = r >> 8, k = r & 255;
        float v = (k < 128) ? W2l[(size_t)k * CH + nn]
                            : W2r[(size_t)(k - 128) * CH + nn];
        g_W2t[nn * 256 + k] = __float2half(v);
    } else if (idx < 81920) {
        int r = idx - 65536;
        int nn = r >> 7, k = r & 127;
        g_Wdt[nn * 128 + k] = __float2half(Wd[(size_t)k * CH + nn]);
    }
}

// ---------------------------------------------------------------------------
// CSR build: histogram -> scan -> fill (proven R11)
// ---------------------------------------------------------------------------
__global__ void clear_cnt_kernel(int n) {
    int i = blockIdx.x * blockDim.x + threadIdx.x;
    if (i < n) g_cnt[i] = 0;
}

__global__ void hist_kernel(const void* __restrict__ edge, int E, int n) {
    int i = blockIdx.x * blockDim.x + threadIdx.x;
    if (i >= E) return;
    int d = edge_at(edge, E + i);
    if ((unsigned)d < (unsigned)n) atomicAdd(&g_cnt[d], 1);
}

__global__ void scan1_kernel(int n) {
    __shared__ int sh[1024];
    int t = threadIdx.x;
    int idx = blockIdx.x * 1024 + t;
    int v = (idx < n) ? g_cnt[idx] : 0;
    sh[t] = v;
    __syncthreads();
    #pragma unroll
    for (int off = 1; off < 1024; off <<= 1) {
        int add = (t >= off) ? sh[t - off] : 0;
        __syncthreads();
        sh[t] += add;
        __syncthreads();
    }
    if (idx < n) g_row[idx] = sh[t] - v;
    if (t == 1023) g_bsum[blockIdx.x] = sh[1023];
}

__global__ void scan2_kernel(int nb) {
    __shared__ int sh[64];
    int t = threadIdx.x;
    sh[t] = (t < nb) ? g_bsum[t] : 0;
    __syncthreads();
    if (t == 0) {
        int run = 0;
        for (int i = 0; i < nb; i++) {
            g_boff[i] = run;
            run += sh[i];
        }
    }
}

__global__ void scan3_kernel(int n, int E) {
    int idx = blockIdx.x * 1024 + threadIdx.x;
    if (idx < n) {
        g_row[idx] += g_boff[blockIdx.x];
        g_cursor[idx] = 0;
    }
    if (idx == 0) g_row[n] = E;
}

__global__ void fill_kernel(const void* __restrict__ edge, int E, int n) {
    int i = blockIdx.x * blockDim.x + threadIdx.x;
    if (i >= E) return;
    int s = edge_at(edge, i);
    int d = edge_at(edge, E + i);
    if ((unsigned)d >= (unsigned)n) return;
    if ((unsigned)s >= (unsigned)n) s = 0;
    int pos = g_row[d] + atomicAdd(&g_cursor[d], 1);
    g_col[pos] = s;
}

// ---------------------------------------------------------------------------
// aggregate: one warp per destination row, fp16 gather, fp32 accumulate,
// mean folded in, fp16 output. SRC 0: g_xh. SRC 1: g_h1h. -> g_aggh.
// ---------------------------------------------------------------------------
template <int SRC>
__global__ void aggregate_kernel(int n) {
    int row = (blockIdx.x * blockDim.x + threadIdx.x) >> 5;
    int lane = threadIdx.x & 31;
    if (row >= n) return;

    const __half* __restrict__ feat = (SRC == 0) ? g_xh : g_h1h;

    int base = g_row[row];
    int end  = g_row[row + 1];
    int deg  = end - base;

    float a0 = 0.f, a1 = 0.f, a2 = 0.f, a3 = 0.f;
    int j = base;
    for (; j + 3 < end; j += 4) {
        int s0 = g_col[j],     s1 = g_col[j + 1];
        int s2 = g_col[j + 2], s3 = g_col[j + 3];
        uint2 u0 = *(const uint2*)(feat + (size_t)s0 * CH + lane * 4);
        uint2 u1 = *(const uint2*)(feat + (size_t)s1 * CH + lane * 4);
        uint2 u2 = *(const uint2*)(feat + (size_t)s2 * CH + lane * 4);
        uint2 u3 = *(const uint2*)(feat + (size_t)s3 * CH + lane * 4);
        float2 f0a = __half22float2(*(__half2*)&u0.x), f0b = __half22float2(*(__half2*)&u0.y);
        float2 f1a = __half22float2(*(__half2*)&u1.x), f1b = __half22float2(*(__half2*)&u1.y);
        float2 f2a = __half22float2(*(__half2*)&u2.x), f2b = __half22float2(*(__half2*)&u2.y);
        float2 f3a = __half22float2(*(__half2*)&u3.x), f3b = __half22float2(*(__half2*)&u3.y);
        a0 += (f0a.x + f1a.x) + (f2a.x + f3a.x);
        a1 += (f0a.y + f1a.y) + (f2a.y + f3a.y);
        a2 += (f0b.x + f1b.x) + (f2b.x + f3b.x);
        a3 += (f0b.y + f1b.y) + (f2b.y + f3b.y);
    }
    for (; j < end; j++) {
        int s0 = g_col[j];
        uint2 u0 = *(const uint2*)(feat + (size_t)s0 * CH + lane * 4);
        float2 fa = __half22float2(*(__half2*)&u0.x), fb = __half22float2(*(__half2*)&u0.y);
        a0 += fa.x; a1 += fa.y; a2 += fb.x; a3 += fb.y;
    }

    float sc = 1.0f / fmaxf((float)deg, 1.0f);
    uint2 o;
    o.x = h2pack(a0 * sc, a1 * sc);
    o.y = h2pack(a2 * sc, a3 * sc);
    *(uint2*)(g_aggh + (size_t)row * CH + lane * 4) = o;
}

// ---------------------------------------------------------------------------
// GEMM via mma.sync m16n8k16 fp16 (HMMA), single pass, fp16 operands
// everywhere (pre-converted). BM=64, BN=128, KC=32. 8 warps 2(M) x 4(N).
// MODE 1: relu( [agg | x ] @ W1t + b1 ) -> g_h1h                  (K=256)
// MODE 2 (FUSED): h2 = relu( [agg | h1] @ W2t + b2 ) kept in smem,
//                 then out = alpha*(h2 @ Wdt + bd) + (1-alpha)*x   (K=128)
// ---------------------------------------------------------------------------
#define BM 64
#define KC 32
#define ASTR 40     // fp16 row stride for staging tiles (conflict-free)
#define H2STR 136   // h2 smem row stride: 68 words == 4 mod 32 -> conflict-free

__device__ __forceinline__ void mma_f16(float* d, const uint32_t* a,
                                        const uint32_t* b) {
    asm volatile(
        "mma.sync.aligned.m16n8k16.row.col.f32.f16.f16.f32 "
        "{%0,%1,%2,%3}, {%4,%5,%6,%7}, {%8,%9}, {%0,%1,%2,%3};"
        : "+f"(d[0]), "+f"(d[1]), "+f"(d[2]), "+f"(d[3])
        : "r"(a[0]), "r"(a[1]), "r"(a[2]), "r"(a[3]), "r"(b[0]), "r"(b[1]));
}

template <int MODE>
__global__ __launch_bounds__(256) void gemm_kernel(
    const float* __restrict__ bias,    // b1 or b2
    const float* __restrict__ bd,      // MODE 2
    const float* __restrict__ xres,    // MODE 2
    const float* __restrict__ alpha_p, // MODE 2
    float* __restrict__ out_ext,       // MODE 2
    int n)
{
    __shared__ __half As[BM][ASTR];
    __shared__ __half Bs[128][ASTR];
    __shared__ __half H2[BM][H2STR];   // MODE 2 only
    __shared__ float s_bias[128];
    __shared__ float s_bd[128];

    int t = threadIdx.x;
    int lane = t & 31;
    int w = t >> 5;
    int wm = w >> 2;
    int wn = w & 3;
    int block_row = blockIdx.x * BM;

    if (t < 128) {
        s_bias[t] = bias[t];
        if (MODE == 2) s_bd[t] = bd[t];
    }

    float acc[2][4][4];
    #pragma unroll
    for (int mi = 0; mi < 2; mi++)
        #pragma unroll
        for (int nj = 0; nj < 4; nj++)
            #pragma unroll
            for (int q = 0; q < 4; q++) acc[mi][nj][q] = 0.f;

    const __half* Wt = (MODE == 1) ? g_W1t : g_W2t;

    int bnn = t >> 1;            // 0..127
    int bks = (t & 1) * 16;      // 0,16

    // ================= GEMM 1: [agg | self] @ Wt =================
    #pragma unroll 1
    for (int c = 0; c < 8; c++) {
        const __half* Asrc = (c < 4) ? g_aggh : ((MODE == 1) ? g_xh : g_h1h);
        int kofsA = (c & 3) * KC;
        __syncthreads();   // previous chunk's mma reads done before restage

        // ---- stage A: pure fp16 copy, 64 rows x 32 k ----
        {
            int row = t >> 2;
            int ks = (t & 3) * 8;
            int grow = block_row + row;
            uint4 v = make_uint4(0, 0, 0, 0);
            if (grow < n)
                v = *(const uint4*)(Asrc + (size_t)grow * CH + kofsA + ks);
            *(uint4*)&As[row][ks] = v;
        }
        // ---- stage B: pure fp16 copy from pre-transposed weights ----
        {
            size_t go = (size_t)bnn * 256 + c * KC + bks;
            *(uint4*)&Bs[bnn][bks]     = *(const uint4*)(Wt + go);
            *(uint4*)&Bs[bnn][bks + 8] = *(const uint4*)(Wt + go + 8);
        }
        __syncthreads();

        // ---- mma: 2 k16-steps ----
        #pragma unroll
        for (int kk = 0; kk < KC; kk += 16) {
            int kw = kk + (lane & 3) * 2;
            int rr = wm * 32 + (lane >> 2);
            uint32_t a_f[2][4], b_f[4][2];
            #pragma unroll
            for (int mi = 0; mi < 2; mi++) {
                int r = rr + mi * 16;
                a_f[mi][0] = *(uint32_t*)&As[r][kw];
                a_f[mi][1] = *(uint32_t*)&As[r + 8][kw];
                a_f[mi][2] = *(uint32_t*)&As[r][kw + 8];
                a_f[mi][3] = *(uint32_t*)&As[r + 8][kw + 8];
            }
            #pragma unroll
            for (int nj = 0; nj < 4; nj++) {
                int cn = wn * 32 + nj * 8 + (lane >> 2);
                b_f[nj][0] = *(uint32_t*)&Bs[cn][kw];
                b_f[nj][1] = *(uint32_t*)&Bs[cn][kw + 8];
            }
            #pragma unroll
            for (int mi = 0; mi < 2; mi++)
                #pragma unroll
                for (int nj = 0; nj < 4; nj++)
                    mma_f16(acc[mi][nj], a_f[mi], b_f[nj]);
        }
    }

    // ================= epilogue 1 =================
    if (MODE == 1) {
        #pragma unroll
        for (int mi = 0; mi < 2; mi++)
            #pragma unroll
            for (int part = 0; part < 2; part++) {
                int grow = block_row + wm * 32 + mi * 16 + part * 8 + (lane >> 2);
                if (grow < n) {
                    #pragma unroll
                    for (int nj = 0; nj < 4; nj++) {
                        int gcol = wn * 32 + nj * 8 + (lane & 3) * 2;
                        float v0 = acc[mi][nj][part * 2 + 0] + s_bias[gcol];
                        float v1 = acc[mi][nj][part * 2 + 1] + s_bias[gcol + 1];
                        *(uint32_t*)(g_h1h + (size_t)grow * CH + gcol) =
                            h2pack(fmaxf(v0, 0.f), fmaxf(v1, 0.f));
                    }
                }
            }
        return;
    }

    // MODE 2: write relu(h2) into smem H2 (stays on-chip)
    __syncthreads();   // last chunk's mma done; As/Bs free, H2 safe to fill
    #pragma unroll
    for (int mi = 0; mi < 2; mi++)
        #pragma unroll
        for (int part = 0; part < 2; part++) {
            int row = wm * 32 + mi * 16 + part * 8 + (lane >> 2);
            #pragma unroll
            for (int nj = 0; nj < 4; nj++) {
                int gcol = wn * 32 + nj * 8 + (lane & 3) * 2;
                float v0 = acc[mi][nj][part * 2 + 0] + s_bias[gcol];
                float v1 = acc[mi][nj][part * 2 + 1] + s_bias[gcol + 1];
                *(uint32_t*)&H2[row][gcol] =
                    h2pack(fmaxf(v0, 0.f), fmaxf(v1, 0.f));
            }
        }

    // ================= GEMM 2 (decoder): H2 @ Wdt =================
    float acc2[2][4][4];
    #pragma unroll
    for (int mi = 0; mi < 2; mi++)
        #pragma unroll
        for (int nj = 0; nj < 4; nj++)
            #pragma unroll
            for (int q = 0; q < 4; q++) acc2[mi][nj][q] = 0.f;

    #pragma unroll 1
    for (int c = 0; c < 4; c++) {
        __syncthreads();   // prior mma reads of Bs done (and H2 ready, c==0)
        {
            size_t go = (size_t)bnn * 128 + c * KC + bks;
            *(uint4*)&Bs[bnn][bks]     = *(const uint4*)(g_Wdt + go);
            *(uint4*)&Bs[bnn][bks + 8] = *(const uint4*)(g_Wdt + go + 8);
        }
        __syncthreads();

        #pragma unroll
        for (int kk = 0; kk < KC; kk += 16) {
            int kwB = kk + (lane & 3) * 2;
            int kwA = c * KC + kwB;
            int rr = wm * 32 + (lane >> 2);
            uint32_t a_f[2][4], b_f[4][2];
            #pragma unroll
            for (int mi = 0; mi < 2; mi++) {
                int r = rr + mi * 16;
                a_f[mi][0] = *(uint32_t*)&H2[r][kwA];
                a_f[mi][1] = *(uint32_t*)&H2[r + 8][kwA];
                a_f[mi][2] = *(uint32_t*)&H2[r][kwA + 8];
                a_f[mi][3] = *(uint32_t*)&H2[r + 8][kwA + 8];
            }
            #pragma unroll
            for (int nj = 0; nj < 4; nj++) {
                int cn = wn * 32 + nj * 8 + (lane >> 2);
                b_f[nj][0] = *(uint32_t*)&Bs[cn][kwB];
                b_f[nj][1] = *(uint32_t*)&Bs[cn][kwB + 8];
            }
            #pragma unroll
            for (int mi = 0; mi < 2; mi++)
                #pragma unroll
                for (int nj = 0; nj < 4; nj++)
                    mma_f16(acc2[mi][nj], a_f[mi], b_f[nj]);
        }
    }

    // ================= epilogue 2: bias + residual =================
    float alpha = *alpha_p;
    float one_m = 1.0f - alpha;
    #pragma unroll
    for (int mi = 0; mi < 2; mi++)
        #pragma unroll
        for (int part = 0; part < 2; part++) {
            int grow = block_row + wm * 32 + mi * 16 + part * 8 + (lane >> 2);
            if (grow < n) {
                #pragma unroll
                for (int nj = 0; nj < 4; nj++) {
                    int gcol = wn * 32 + nj * 8 + (lane & 3) * 2;
                    float v0 = acc2[mi][nj][part * 2 + 0] + s_bd[gcol];
                    float v1 = acc2[mi][nj][part * 2 + 1] + s_bd[gcol + 1];
                    size_t o = (size_t)grow * CH + gcol;
                    float2 xv = *(const float2*)(xres + o);
                    float2 ov;
                    ov.x = alpha * v0 + one_m * xv.x;
                    ov.y = alpha * v1 + one_m * xv.y;
                    *(float2*)(out_ext + o) = ov;
                }
            }
        }
}

// ---------------------------------------------------------------------------
extern "C" void kernel_launch(void* const* d_in, const int* in_sizes, int n_in,
                              void* d_out, int out_size) {
    const float* x     = (const float*)d_in[0];
    const void*  edge  = d_in[1];
    const float* W1_l  = (const float*)d_in[2];
    const float* b1    = (const float*)d_in[3];
    const float* W1_r  = (const float*)d_in[4];
    const float* W2_l  = (const float*)d_in[5];
    const float* b2    = (const float*)d_in[6];
    const float* W2_r  = (const float*)d_in[7];
    const float* Wd    = (const float*)d_in[8];
    const float* bd    = (const float*)d_in[9];
    const float* alpha = (const float*)d_in[10];
    float* out = (float*)d_out;

    int n = in_sizes[0] / CH;            // 50000
    int E = in_sizes[1] / 2;             // 640000
    if (E > EMAX) E = EMAX;

    int eb = (E + 255) / 256;
    int nb = (n + 255) / 256;
    int sb = (n + 1023) / 1024;
    int cb = (n * CH / 8 + 255) / 256;
    int ab = (n * 32 + 255) / 256;
    int gb = (n + BM - 1) / BM;          // 782

    // prep: dtype detect, x->fp16, weights->fp16T, CSR build (once)
    detect_kernel<<<1, 256>>>((const unsigned*)edge);
    convert_x_kernel<<<cb, 256>>>(x, n);
    prep_w_kernel<<<320, 256>>>(W1_l, W1_r, W2_l, W2_r, Wd);
    clear_cnt_kernel<<<nb, 256>>>(n);
    hist_kernel<<<eb, 256>>>(edge, E, n);
    scan1_kernel<<<sb, 1024>>>(n);
    scan2_kernel<<<1, 64>>>(sb);
    scan3_kernel<<<sb, 1024>>>(n, E);
    fill_kernel<<<eb, 256>>>(edge, E, n);

    // Layer 1
    aggregate_kernel<0><<<ab, 256>>>(n);
    gemm_kernel<1><<<gb, 256>>>(b1, nullptr, nullptr, nullptr, nullptr, n);
    // Layer 2 + decoder + residual (fused)
    aggregate_kernel<1><<<ab, 256>>>(n);
    gemm_kernel<2><<<gb, 256>>>(b2, bd, x, alpha, out, n);
}